// round 8
// baseline (speedup 1.0000x reference)
#include <cuda_runtime.h>
#include <math.h>

#define B_   128
#define T_   512
#define NI   64
#define NH   1024
#define NO   64

#define NCTA   132           // 128 rec/fgt CTAs + 4 dec CTAs; 1 CTA/SM
#define NTHR   256
#define BK     64
#define NCHUNK (NH/BK)       // 16
#define NCOL   16            // 16 dup'd weight columns per CTA (8 pairs)
#define SMEM_BYTES (NH*NCOL*8 + 2*BK*B_*4)   // 128KB wdup + 64KB hs = 196608

// ---------------- scratch ------------------------------------------------------
__device__ float g_encT[(size_t)T_ * NH * B_];         // [t][h][b]
__device__ float g_hidT[2][NH * B_];                   // [h][b]
__device__ volatile unsigned g_gen;
__device__ unsigned g_cnt;

// ---------------- helpers ------------------------------------------------------
#define FMA2(d, a, b) asm("fma.rn.f32x2 %0, %1, %2, %0;" : "+l"(d) : "l"(a), "l"(b))
__device__ __forceinline__ unsigned long long dup2(float h) {
    unsigned long long r;
    asm("mov.b64 %0, {%1, %1};" : "=l"(r) : "f"(h));
    return r;
}
__device__ __forceinline__ float u64lo(unsigned long long v) { return __uint_as_float((unsigned)v); }
__device__ __forceinline__ float u64hi(unsigned long long v) { return __uint_as_float((unsigned)(v >> 32)); }

__device__ __forceinline__ void grid_barrier() {
    __threadfence();
    __syncthreads();
    if (threadIdx.x == 0) {
        unsigned gen = g_gen;
        if (atomicAdd(&g_cnt, 1) == NCTA - 1) {
            g_cnt = 0;
            __threadfence();
            g_gen = gen + 1;
        } else {
            while (g_gen == gen) __nanosleep(16);
        }
        __threadfence();
    }
    __syncthreads();
}

// ---------------- reset + init --------------------------------------------------
__global__ void reset_kernel() {
    if (threadIdx.x == 0) { g_gen = 0; g_cnt = 0; }
}

__global__ void init_hidden_kernel(const float* __restrict__ hinit_w,
                                   const float* __restrict__ hinit_b) {
    int idx = blockIdx.x * blockDim.x + threadIdx.x;
    if (idx < B_ * NH) {
        int h = idx >> 7;                  // [h][b]
        g_hidT[0][idx] = hinit_w[h] + hinit_b[h];
    }
}

// ---------------- encoder GEMM (one-shot), writes transposed [t][h][b] ----------
__global__ void __launch_bounds__(256) enc_kernel(const float* __restrict__ x,
                                                  const float* __restrict__ enc_w,
                                                  const float* __restrict__ enc_b) {
    __shared__ float xs[32][NI + 1];
    __shared__ float ws[64][NI + 1];
    const int tid = threadIdx.x;
    const int tb0 = blockIdx.x * 32;
    const int h0  = blockIdx.y * 64;

    for (int i = tid; i < 32 * NI; i += 256) {
        int r = i >> 6, c = i & 63;
        int tb = tb0 + r;
        int t = tb >> 7, b = tb & 127;
        xs[r][c] = x[(size_t)b * (T_ * NI) + t * NI + c];
    }
    for (int i = tid; i < 64 * NI; i += 256) {
        int r = i >> 6, c = i & 63;
        ws[r][c] = enc_w[(h0 + r) * NI + c];
    }
    __syncthreads();

    const int rg = tid & 7;
    const int hg = tid >> 3;
    float acc[4][2] = {};
#pragma unroll
    for (int k = 0; k < NI; k++) {
        float w0 = ws[hg * 2 + 0][k];
        float w1 = ws[hg * 2 + 1][k];
#pragma unroll
        for (int j = 0; j < 4; j++) {
            float xv = xs[rg * 4 + j][k];
            acc[j][0] += xv * w0;
            acc[j][1] += xv * w1;
        }
    }
#pragma unroll
    for (int j = 0; j < 4; j++) {
        int tb = tb0 + rg * 4 + j;
        int t = tb >> 7, b = tb & 127;
#pragma unroll
        for (int q = 0; q < 2; q++) {
            int h = h0 + hg * 2 + q;
            g_encT[((size_t)t * NH + h) * B_ + b] = acc[j][q] + enc_b[h];
        }
    }
}

// ---------------- persistent recurrent kernel ------------------------------------
// CTA jt = bid: jt<128 -> owns h columns jt*8..jt*8+7 (cols interleaved R0,F0,..,R7,F7).
//               jt>=128 -> dec CTA d=jt-128, owns out cols d*16..d*16+15.
// Full K=1024 per CTA: no cross-CTA reduction. One grid barrier per step.
__global__ void __launch_bounds__(NTHR) persist_kernel(const float* __restrict__ rec_w,
                                                       const float* __restrict__ fgt_w,
                                                       const float* __restrict__ dec_w,
                                                       const float* __restrict__ dec_b,
                                                       float* __restrict__ out,
                                                       int writeHidden) {
    extern __shared__ __align__(16) char smem[];
    unsigned long long* wdup = (unsigned long long*)smem;    // [1024 k][16 c] dup'd
    float* hs = (float*)(smem + NH * NCOL * 8);              // [2][64 k][128 b]

    const int tid = threadIdx.x;
    const int jt  = blockIdx.x;
    const bool isDec = (jt >= 128);

    const int cg = tid & 7;          // col group: cols cg*2, cg*2+1
    const int bg = tid >> 3;         // b group: b = bg*4..bg*4+3
    const int b0 = bg * 4;

    // ---- weights -> SMEM once, pre-duplicated ----
    for (int i = tid; i < NH * NCOL; i += NTHR) {
        int k = i >> 4, c = i & 15;
        float v;
        if (!isDec) {
            int p = jt * 8 + (c >> 1);
            v = (c & 1) ? fgt_w[p * NH + k] : rec_w[p * NH + k];
        } else {
            int ocol = (jt - 128) * 16 + c;
            v = dec_w[ocol * NH + k];
        }
        wdup[i] = dup2(v);
    }
    __syncthreads();

    // dec bias preload
    float dbv0 = 0.f, dbv1 = 0.f;
    if (isDec) {
        dbv0 = dec_b[(jt - 128) * 16 + cg * 2];
        dbv1 = dec_b[(jt - 128) * 16 + cg * 2 + 1];
    }
    const int hcol = jt * 8 + cg;    // rec: global h column this thread finalizes

    for (int t = 0; t <= T_; t++) {
        const int cur = t & 1, nxt = (t + 1) & 1;
        const bool work = isDec || (t < T_);

        if (work) {
            const float* __restrict__ hsrc = g_hidT[cur];

            // early prefetch of epilogue operands (rec only)
            float4 e4, ho4;
            if (!isDec) {
                e4  = __ldcg((const float4*)(g_encT + ((size_t)t * NH + hcol) * B_ + b0));
                ho4 = __ldcg((const float4*)(hsrc + hcol * B_ + b0));
            }

            // ---- prologue: stage chunk 0 ----
            float4 pf[8];
#pragma unroll
            for (int i = 0; i < 8; i++) {
                int slot = i * NTHR + tid;
                int row = slot >> 5, c4 = slot & 31;
                pf[i] = __ldcg((const float4*)(hsrc + row * B_ + c4 * 4));
            }
#pragma unroll
            for (int i = 0; i < 8; i++) {
                int slot = i * NTHR + tid;
                int row = slot >> 5, c4 = slot & 31;
                *(float4*)(hs + row * B_ + c4 * 4) = pf[i];
            }

            ulonglong2 accC0, accC1;
            accC0.x = accC0.y = accC1.x = accC1.y = 0ull;

            for (int kc = 0; kc < NCHUNK; kc++) {
                if (kc + 1 < NCHUNK) {
#pragma unroll
                    for (int i = 0; i < 8; i++) {
                        int slot = i * NTHR + tid;
                        int row = slot >> 5, c4 = slot & 31;
                        pf[i] = __ldcg((const float4*)(hsrc + ((kc + 1) * BK + row) * B_ + c4 * 4));
                    }
                }
                __syncthreads();
                if (kc + 1 < NCHUNK) {
                    float* hb = hs + ((kc + 1) & 1) * (BK * B_);
#pragma unroll
                    for (int i = 0; i < 8; i++) {
                        int slot = i * NTHR + tid;
                        int row = slot >> 5, c4 = slot & 31;
                        *(float4*)(hb + row * B_ + c4 * 4) = pf[i];
                    }
                }
                const float* hb = hs + (kc & 1) * (BK * B_);
                const unsigned long long* wb = wdup + (size_t)kc * BK * NCOL + cg * 2;
#pragma unroll 16
                for (int kk = 0; kk < BK; kk++) {
                    ulonglong2 hh = *(const ulonglong2*)(hb + kk * B_ + b0);
                    ulonglong2 ww = *(const ulonglong2*)(wb + kk * NCOL);
                    FMA2(accC0.x, hh.x, ww.x);
                    FMA2(accC0.y, hh.y, ww.x);
                    FMA2(accC1.x, hh.x, ww.y);
                    FMA2(accC1.y, hh.y, ww.y);
                }
            }

            // ---- fused epilogue (fully reduced in-registers) ----
            if (!isDec) {
                float R[4] = {u64lo(accC0.x), u64hi(accC0.x), u64lo(accC0.y), u64hi(accC0.y)};
                float F[4] = {u64lo(accC1.x), u64hi(accC1.x), u64lo(accC1.y), u64hi(accC1.y)};
                const float ev[4]  = {e4.x, e4.y, e4.z, e4.w};
                const float hov[4] = {ho4.x, ho4.y, ho4.z, ho4.w};
                float hv[4];
#pragma unroll
                for (int i = 0; i < 4; i++) {
                    float f = 1.0f / (1.0f + __expf(-F[i]));
                    float s = ev[i] + R[i];
                    float hn = s / (1.0f + fabsf(s));
                    hv[i] = (1.0f - f) * hov[i] + f * hn;
                }
                *(float4*)(g_hidT[nxt] + hcol * B_ + b0) = make_float4(hv[0], hv[1], hv[2], hv[3]);
            } else if (t >= 1) {
                int oc0 = (jt - 128) * 16 + cg * 2;
                float* op = out + (size_t)(t - 1) * (B_ * NO);
                float v0[4] = {u64lo(accC0.x), u64hi(accC0.x), u64lo(accC0.y), u64hi(accC0.y)};
                float v1[4] = {u64lo(accC1.x), u64hi(accC1.x), u64lo(accC1.y), u64hi(accC1.y)};
#pragma unroll
                for (int i = 0; i < 4; i++) {
                    op[(b0 + i) * NO + oc0]     = v0[i] + dbv0;
                    op[(b0 + i) * NO + oc0 + 1] = v1[i] + dbv1;
                }
            }
        }

        if (t == T_) break;
        grid_barrier();
    }

    // ---- final hidden copy to out tail [b][h] ----
    if (writeHidden && !isDec) {
        float4 hv = *(const float4*)(g_hidT[0] + hcol * B_ + b0);
        float* dst = out + (size_t)T_ * B_ * NO;
        dst[(size_t)(b0 + 0) * NH + hcol] = hv.x;
        dst[(size_t)(b0 + 1) * NH + hcol] = hv.y;
        dst[(size_t)(b0 + 2) * NH + hcol] = hv.z;
        dst[(size_t)(b0 + 3) * NH + hcol] = hv.w;
    }
}

// --------------------------------------------------------------------------------
extern "C" void kernel_launch(void* const* d_in, const int* in_sizes, int n_in,
                              void* d_out, int out_size) {
    const float* x       = (const float*)d_in[0];
    const float* enc_w   = (const float*)d_in[1];
    const float* enc_b   = (const float*)d_in[2];
    const float* rec_w   = (const float*)d_in[3];
    const float* fgt_w   = (const float*)d_in[4];
    const float* dec_w   = (const float*)d_in[5];
    const float* dec_b   = (const float*)d_in[6];
    const float* hinit_w = (const float*)d_in[7];
    const float* hinit_b = (const float*)d_in[8];
    float* out = (float*)d_out;

    reset_kernel<<<1, 32>>>();
    init_hidden_kernel<<<(B_ * NH + 255) / 256, 256>>>(hinit_w, hinit_b);

    dim3 eg(T_ * B_ / 32, NH / 64);
    enc_kernel<<<eg, 256>>>(x, enc_w, enc_b);

    cudaFuncSetAttribute(persist_kernel, cudaFuncAttributeMaxDynamicSharedMemorySize,
                         SMEM_BYTES);
    int writeHidden = (out_size >= T_ * B_ * NO + B_ * NH) ? 1 : 0;
    persist_kernel<<<NCTA, NTHR, SMEM_BYTES>>>(rec_w, fgt_w, dec_w, dec_b, out, writeHidden);
}

// round 9
// speedup vs baseline: 1.8445x; 1.8445x over previous
#include <cuda_runtime.h>
#include <math.h>

#define B_   128
#define T_   512
#define NI   64
#define NH   1024
#define NO   64

#define NJT    33            // 32 rec/fgt j-tiles + 1 dec j-tile
#define KSPLIT 8
#define NCTA   (NJT*KSPLIT)  // 264
#define NTHR   128
#define KSL    128           // k-slice per CTA
#define BK     16
#define NCHUNK (KSL/BK)      // 8
#define JP_CTA 32            // column-pairs per CTA
#define OUTS_CTA 4096        // 128 b * 32 pairs
#define PARTBUF ((size_t)NCTA * OUTS_CTA)
#define SMEM_BYTES (KSL*JP_CTA*8 + 2*BK*B_*4)   // 32KB ws + 16KB hs = 48KB

// ---------------- scratch ------------------------------------------------------
__device__ float g_enc[(size_t)T_ * B_ * NH];          // [t][b][h]
__device__ float g_hidB[3][B_ * NH];                   // [b][h], triple-buffered
__device__ float g_hidT[3][NH * B_];                   // [h][b], triple-buffered
__device__ unsigned long long g_part[2 * PARTBUF];     // step-parity double buffer
__device__ unsigned g_flag[NJT];                       // publish counters
__device__ unsigned g_done[32];                        // per-rec-tile hidden-ready
__device__ unsigned g_decc[8];                         // dec consumption per k-slot

// ---------------- helpers ------------------------------------------------------
#define FMA2(d, a, b) asm("fma.rn.f32x2 %0, %1, %2, %0;" : "+l"(d) : "l"(a), "l"(b))
__device__ __forceinline__ unsigned long long dup2(float h) {
    unsigned long long r;
    asm("mov.b64 %0, {%1, %1};" : "=l"(r) : "f"(h));
    return r;
}

// ---------------- reset + init --------------------------------------------------
__global__ void reset_kernel() {
    int i = threadIdx.x;
    if (i < NJT) g_flag[i] = 0;
    if (i < 32) g_done[i] = 0;
    if (i < 8)  g_decc[i] = 0;
}

__global__ void init_hidden_kernel(const float* __restrict__ hinit_w,
                                   const float* __restrict__ hinit_b) {
    int idx = blockIdx.x * blockDim.x + threadIdx.x;
    if (idx < B_ * NH) {
        int hT = idx >> 7;                 // [h][b]
        g_hidT[0][idx] = hinit_w[hT] + hinit_b[hT];
        int hB = idx & (NH - 1);           // [b][h]
        g_hidB[0][idx] = hinit_w[hB] + hinit_b[hB];
    }
}

// ---------------- encoder GEMM (one-shot) ---------------------------------------
__global__ void __launch_bounds__(256) enc_kernel(const float* __restrict__ x,
                                                  const float* __restrict__ enc_w,
                                                  const float* __restrict__ enc_b) {
    __shared__ float xs[32][NI + 1];
    __shared__ float ws[64][NI + 1];
    const int tid = threadIdx.x;
    const int tb0 = blockIdx.x * 32;
    const int h0  = blockIdx.y * 64;

    for (int i = tid; i < 32 * NI; i += 256) {
        int r = i >> 6, c = i & 63;
        int tb = tb0 + r;
        int t = tb >> 7, b = tb & 127;
        xs[r][c] = x[(size_t)b * (T_ * NI) + t * NI + c];
    }
    for (int i = tid; i < 64 * NI; i += 256) {
        int r = i >> 6, c = i & 63;
        ws[r][c] = enc_w[(h0 + r) * NI + c];
    }
    __syncthreads();

    const int rg = tid & 7;
    const int hg = tid >> 3;
    float acc[4][2] = {};
#pragma unroll
    for (int k = 0; k < NI; k++) {
        float w0 = ws[hg * 2 + 0][k];
        float w1 = ws[hg * 2 + 1][k];
#pragma unroll
        for (int j = 0; j < 4; j++) {
            float xv = xs[rg * 4 + j][k];
            acc[j][0] += xv * w0;
            acc[j][1] += xv * w1;
        }
    }
#pragma unroll
    for (int j = 0; j < 4; j++) {
        int tb = tb0 + rg * 4 + j;
#pragma unroll
        for (int q = 0; q < 2; q++) {
            int h = h0 + hg * 2 + q;
            g_enc[(size_t)tb * NH + h] = acc[j][q] + enc_b[h];
        }
    }
}

// ---------------- persistent recurrent kernel ------------------------------------
// CTA: jt = bid>>3 (j-tile of 32 pairs), ks = bid&7 (k-slot of 128).
// Pair p = jt*32+jp: p<1024 -> (rec_w[p,:], fgt_w[p,:]); p>=1024 -> dec cols (2m,2m+1).
// No global barrier: per-tile dataflow flags; hidden triple-buffered; partials
// double-buffered by step parity.
__global__ void __launch_bounds__(NTHR) persist_kernel(const float* __restrict__ rec_w,
                                                       const float* __restrict__ fgt_w,
                                                       const float* __restrict__ dec_w,
                                                       const float* __restrict__ dec_b,
                                                       float* __restrict__ out,
                                                       int writeHidden) {
    extern __shared__ __align__(16) char smem[];
    unsigned long long* ws = (unsigned long long*)smem;     // [128 k][32 jp] (wA,wB)
    float* hsf = (float*)(smem + KSL * JP_CTA * 8);         // [2][16 k][128 b]

    const int tid = threadIdx.x;
    const int bid = blockIdx.x;
    const int jt  = bid >> 3;        // 0..32
    const int ks  = bid & 7;         // 0..7
    const int j0  = jt * JP_CTA;
    const int kbase = ks * KSL;
    const bool isDec = (jt == 32);

    const int jg = tid & 7;          // 8 j-groups of 4 pairs
    const int bg = tid >> 3;         // 16 b-groups of 8 rows

    // ---- weights -> SMEM once ----
    for (int i = tid; i < KSL * JP_CTA; i += NTHR) {
        int k = i & (KSL - 1), jp = i >> 7;
        int p = j0 + jp;
        int gk = kbase + k;
        float a, b;
        if (p < 1024) { a = rec_w[p * NH + gk]; b = fgt_w[p * NH + gk]; }
        else { int m = p - 1024; a = dec_w[(2 * m) * NH + gk]; b = dec_w[(2 * m + 1) * NH + gk]; }
        ws[k * JP_CTA + jp] = ((unsigned long long)__float_as_uint(b) << 32) | __float_as_uint(a);
    }
    __syncthreads();

    // combine-phase identities
    const int bloc = ks * 16 + (tid >> 3);   // b this thread combines
    const int jpb  = (tid & 7) * 4;          // 4 consecutive jp
    float4 db0 = make_float4(0, 0, 0, 0), db1 = db0;
    if (isDec) {
        db0 = *(const float4*)(dec_b + jpb * 2);
        db1 = *(const float4*)(dec_b + jpb * 2 + 4);
    }

    int cur = 0;
    for (int t = 0; t <= T_; t++) {
        const int nxt = (cur + 1 == 3) ? 0 : cur + 1;
        const bool work = (t < T_) || isDec;

        if (work) {
            // ---- wait: producer tiles of this k-slot reached level t ----
            if (tid == 0) {
                unsigned target = 8u * (unsigned)t;
#pragma unroll
                for (int j = 0; j < 4; j++) {
                    while (((volatile unsigned*)g_done)[4 * ks + j] < target) __nanosleep(20);
                }
                __threadfence();
            }
            __syncthreads();

            // ================= GEMM over K-slice =================
            const float* __restrict__ hsrc = g_hidT[cur] + kbase * B_;
            float4 pf[4];
#pragma unroll
            for (int i = 0; i < 4; i++) {
                int slot = i * NTHR + tid;
                int row = slot >> 5, c4 = slot & 31;
                pf[i] = __ldcg((const float4*)(hsrc + row * B_ + c4 * 4));
            }
#pragma unroll
            for (int i = 0; i < 4; i++) {
                int slot = i * NTHR + tid;
                int row = slot >> 5, c4 = slot & 31;
                *(float4*)(hsf + row * B_ + c4 * 4) = pf[i];
            }

            ulonglong2 acc[8][2];
#pragma unroll
            for (int ib = 0; ib < 8; ib++)
#pragma unroll
                for (int jj = 0; jj < 2; jj++) { acc[ib][jj].x = 0ull; acc[ib][jj].y = 0ull; }

            for (int kc = 0; kc < NCHUNK; kc++) {
                if (kc + 1 < NCHUNK) {
#pragma unroll
                    for (int i = 0; i < 4; i++) {
                        int slot = i * NTHR + tid;
                        int row = slot >> 5, c4 = slot & 31;
                        pf[i] = __ldcg((const float4*)(hsrc + ((kc + 1) * BK + row) * B_ + c4 * 4));
                    }
                }
                __syncthreads();
                if (kc + 1 < NCHUNK) {
                    float* hb = hsf + ((kc + 1) & 1) * (BK * B_);
#pragma unroll
                    for (int i = 0; i < 4; i++) {
                        int slot = i * NTHR + tid;
                        int row = slot >> 5, c4 = slot & 31;
                        *(float4*)(hb + row * B_ + c4 * 4) = pf[i];
                    }
                }
                const float* hb = hsf + (kc & 1) * (BK * B_);
#pragma unroll
                for (int kk = 0; kk < BK; kk++) {
                    const float* hr = hb + kk * B_ + bg * 8;
                    float4 h0 = *(const float4*)hr;
                    float4 h1 = *(const float4*)(hr + 4);
                    const ulonglong2* wr = (const ulonglong2*)(ws + (kc * BK + kk) * JP_CTA + jg * 4);
                    ulonglong2 w0 = wr[0];
                    ulonglong2 w1 = wr[1];
                    unsigned long long d0 = dup2(h0.x), d1 = dup2(h0.y), d2 = dup2(h0.z), d3 = dup2(h0.w);
                    unsigned long long d4 = dup2(h1.x), d5 = dup2(h1.y), d6 = dup2(h1.z), d7 = dup2(h1.w);
                    FMA2(acc[0][0].x, d0, w0.x); FMA2(acc[0][0].y, d0, w0.y); FMA2(acc[0][1].x, d0, w1.x); FMA2(acc[0][1].y, d0, w1.y);
                    FMA2(acc[1][0].x, d1, w0.x); FMA2(acc[1][0].y, d1, w0.y); FMA2(acc[1][1].x, d1, w1.x); FMA2(acc[1][1].y, d1, w1.y);
                    FMA2(acc[2][0].x, d2, w0.x); FMA2(acc[2][0].y, d2, w0.y); FMA2(acc[2][1].x, d2, w1.x); FMA2(acc[2][1].y, d2, w1.y);
                    FMA2(acc[3][0].x, d3, w0.x); FMA2(acc[3][0].y, d3, w0.y); FMA2(acc[3][1].x, d3, w1.x); FMA2(acc[3][1].y, d3, w1.y);
                    FMA2(acc[4][0].x, d4, w0.x); FMA2(acc[4][0].y, d4, w0.y); FMA2(acc[4][1].x, d4, w1.x); FMA2(acc[4][1].y, d4, w1.y);
                    FMA2(acc[5][0].x, d5, w0.x); FMA2(acc[5][0].y, d5, w0.y); FMA2(acc[5][1].x, d5, w1.x); FMA2(acc[5][1].y, d5, w1.y);
                    FMA2(acc[6][0].x, d6, w0.x); FMA2(acc[6][0].y, d6, w0.y); FMA2(acc[6][1].x, d6, w1.x); FMA2(acc[6][1].y, d6, w1.y);
                    FMA2(acc[7][0].x, d7, w0.x); FMA2(acc[7][0].y, d7, w0.y); FMA2(acc[7][1].x, d7, w1.x); FMA2(acc[7][1].y, d7, w1.y);
                }
            }

            // ---- publish partials into step-parity slab ----
            unsigned long long* mypart = g_part + (size_t)(t & 1) * PARTBUF + (size_t)bid * OUTS_CTA;
#pragma unroll
            for (int ib = 0; ib < 8; ib++) {
                int b = bg * 8 + ib;
#pragma unroll
                for (int jj = 0; jj < 2; jj++)
                    *(ulonglong2*)(mypart + b * JP_CTA + jg * 4 + jj * 2) = acc[ib][jj];
            }
            __threadfence();
            __syncthreads();
            if (tid == 0) {
                if (isDec) atomicAdd(&g_decc[ks], 1u);   // hidden k-slice consumed
                atomicAdd(&g_flag[jt], 1u);
                unsigned target = 8u * (unsigned)(t + 1);
                while (((volatile unsigned*)g_flag)[jt] < target) __nanosleep(20);
                if (!isDec && t >= 2) {                  // dec readers of buf (t+1)%3 done?
                    unsigned dtarget = (unsigned)(t - 1);
                    while (((volatile unsigned*)g_decc)[jt >> 2] < dtarget) __nanosleep(20);
                }
                __threadfence();
            }
            __syncthreads();

            // ---- combine 8 k-slots + fused epilogue ----
            float R[4] = {0, 0, 0, 0}, F[4] = {0, 0, 0, 0};
            const unsigned long long* gp = g_part + (size_t)(t & 1) * PARTBUF +
                                           (size_t)(jt * KSPLIT) * OUTS_CTA + bloc * JP_CTA + jpb;
#pragma unroll
            for (int k2 = 0; k2 < KSPLIT; k2++) {
                uint4 q0 = __ldcg((const uint4*)(gp + (size_t)k2 * OUTS_CTA));
                uint4 q1 = __ldcg((const uint4*)(gp + (size_t)k2 * OUTS_CTA + 2));
                R[0] += __uint_as_float(q0.x); F[0] += __uint_as_float(q0.y);
                R[1] += __uint_as_float(q0.z); F[1] += __uint_as_float(q0.w);
                R[2] += __uint_as_float(q1.x); F[2] += __uint_as_float(q1.y);
                R[3] += __uint_as_float(q1.z); F[3] += __uint_as_float(q1.w);
            }

            if (!isDec) {
                int hg0 = j0 + jpb;
                float4 e  = __ldcg((const float4*)(g_enc + (size_t)t * (B_ * NH) + bloc * NH + hg0));
                float4 ho = __ldcg((const float4*)(g_hidB[cur] + bloc * NH + hg0));
                float hv[4];
                const float ev[4] = {e.x, e.y, e.z, e.w};
                const float hov[4] = {ho.x, ho.y, ho.z, ho.w};
#pragma unroll
                for (int i = 0; i < 4; i++) {
                    float f = 1.0f / (1.0f + __expf(-F[i]));
                    float s = ev[i] + R[i];
                    float hn = s / (1.0f + fabsf(s));
                    hv[i] = (1.0f - f) * hov[i] + f * hn;
                }
                *(float4*)(g_hidB[nxt] + bloc * NH + hg0) = make_float4(hv[0], hv[1], hv[2], hv[3]);
#pragma unroll
                for (int i = 0; i < 4; i++)
                    g_hidT[nxt][(hg0 + i) * B_ + bloc] = hv[i];

                // ---- signal: this tile's hidden share for step t+1 is ready ----
                __threadfence();
                __syncthreads();
                if (tid == 0) atomicAdd(&g_done[jt], 1u);
            } else if (t >= 1) {
                float4 v0 = make_float4(R[0] + db0.x, F[0] + db0.y, R[1] + db0.z, F[1] + db0.w);
                float4 v1 = make_float4(R[2] + db1.x, F[2] + db1.y, R[3] + db1.z, F[3] + db1.w);
                float* op = out + (size_t)(t - 1) * (B_ * NO) + bloc * NO + jpb * 2;
                *(float4*)op = v0;
                *(float4*)(op + 4) = v1;
            }
        }

        if (t == T_) break;
        cur = nxt;
    }

    // ---- final hidden copy: each CTA copies its own tile's h-columns ----
    if (writeHidden && !isDec) {
        if (tid == 0) {
            unsigned target = 8u * (unsigned)T_;
            while (((volatile unsigned*)g_done)[jt] < target) __nanosleep(20);
            __threadfence();
        }
        __syncthreads();
        int b = ks * 16 + (tid >> 3);
        int h = jt * 32 + (tid & 7) * 4;
        float4 hv = *(const float4*)(g_hidB[cur] + b * NH + h);
        *(float4*)(out + (size_t)T_ * B_ * NO + (size_t)b * NH + h) = hv;
    }
}

// --------------------------------------------------------------------------------
extern "C" void kernel_launch(void* const* d_in, const int* in_sizes, int n_in,
                              void* d_out, int out_size) {
    const float* x       = (const float*)d_in[0];
    const float* enc_w   = (const float*)d_in[1];
    const float* enc_b   = (const float*)d_in[2];
    const float* rec_w   = (const float*)d_in[3];
    const float* fgt_w   = (const float*)d_in[4];
    const float* dec_w   = (const float*)d_in[5];
    const float* dec_b   = (const float*)d_in[6];
    const float* hinit_w = (const float*)d_in[7];
    const float* hinit_b = (const float*)d_in[8];
    float* out = (float*)d_out;

    reset_kernel<<<1, 64>>>();
    init_hidden_kernel<<<(B_ * NH + 255) / 256, 256>>>(hinit_w, hinit_b);

    dim3 eg(T_ * B_ / 32, NH / 64);
    enc_kernel<<<eg, 256>>>(x, enc_w, enc_b);

    cudaFuncSetAttribute(persist_kernel, cudaFuncAttributeMaxDynamicSharedMemorySize,
                         SMEM_BYTES);
    int writeHidden = (out_size >= T_ * B_ * NO + B_ * NH) ? 1 : 0;
    persist_kernel<<<NCTA, NTHR, SMEM_BYTES>>>(rec_w, fgt_w, dec_w, dec_b, out, writeHidden);
}

// round 10
// speedup vs baseline: 1.8885x; 1.0238x over previous
#include <cuda_runtime.h>
#include <math.h>

#define B_   128
#define T_   512
#define NI   64
#define NH   1024
#define NO   64

#define NJT    33            // 32 rec/fgt j-tiles + 1 dec j-tile
#define KSPLIT 16
#define NCTA   (NJT*KSPLIT)  // 528 -> 4 CTAs/SM co-resident (148 SMs)
#define NTHR   128
#define KSL    64            // k-slice per CTA
#define BK     16
#define NCHUNK (KSL/BK)      // 4
#define JP_CTA 32            // column-pairs per CTA
#define OUTS_CTA 4096        // 128 b * 32 pairs
#define PARTBUF ((size_t)NCTA * OUTS_CTA)
#define SMEM_BYTES (KSL*JP_CTA*8 + 2*BK*B_*4)   // 16KB ws + 16KB hs = 32KB

// ---------------- scratch ------------------------------------------------------
__device__ float g_enc[(size_t)T_ * B_ * NH];          // [t][b][h]
__device__ float g_hidB[3][B_ * NH];                   // [b][h], triple-buffered
__device__ float g_hidT[3][NH * B_];                   // [h][b], triple-buffered
__device__ unsigned long long g_part[2 * PARTBUF];     // step-parity double buffer
__device__ unsigned g_flag[NJT];                       // publish counters per tile
__device__ unsigned g_done[32];                        // per-rec-tile hidden-ready
__device__ unsigned g_decc[KSPLIT];                    // dec consumption per k-slot

// ---------------- helpers ------------------------------------------------------
#define FMA2(d, a, b) asm("fma.rn.f32x2 %0, %1, %2, %0;" : "+l"(d) : "l"(a), "l"(b))
__device__ __forceinline__ unsigned long long dup2(float h) {
    unsigned long long r;
    asm("mov.b64 %0, {%1, %1};" : "=l"(r) : "f"(h));
    return r;
}

// ---------------- reset + init --------------------------------------------------
__global__ void reset_kernel() {
    int i = threadIdx.x;
    if (i < NJT) g_flag[i] = 0;
    if (i < 32) g_done[i] = 0;
    if (i < KSPLIT) g_decc[i] = 0;
}

__global__ void init_hidden_kernel(const float* __restrict__ hinit_w,
                                   const float* __restrict__ hinit_b) {
    int idx = blockIdx.x * blockDim.x + threadIdx.x;
    if (idx < B_ * NH) {
        int hT = idx >> 7;                 // [h][b]
        g_hidT[0][idx] = hinit_w[hT] + hinit_b[hT];
        int hB = idx & (NH - 1);           // [b][h]
        g_hidB[0][idx] = hinit_w[hB] + hinit_b[hB];
    }
}

// ---------------- encoder GEMM (one-shot) ---------------------------------------
__global__ void __launch_bounds__(256) enc_kernel(const float* __restrict__ x,
                                                  const float* __restrict__ enc_w,
                                                  const float* __restrict__ enc_b) {
    __shared__ float xs[32][NI + 1];
    __shared__ float ws[64][NI + 1];
    const int tid = threadIdx.x;
    const int tb0 = blockIdx.x * 32;
    const int h0  = blockIdx.y * 64;

    for (int i = tid; i < 32 * NI; i += 256) {
        int r = i >> 6, c = i & 63;
        int tb = tb0 + r;
        int t = tb >> 7, b = tb & 127;
        xs[r][c] = x[(size_t)b * (T_ * NI) + t * NI + c];
    }
    for (int i = tid; i < 64 * NI; i += 256) {
        int r = i >> 6, c = i & 63;
        ws[r][c] = enc_w[(h0 + r) * NI + c];
    }
    __syncthreads();

    const int rg = tid & 7;
    const int hg = tid >> 3;
    float acc[4][2] = {};
#pragma unroll
    for (int k = 0; k < NI; k++) {
        float w0 = ws[hg * 2 + 0][k];
        float w1 = ws[hg * 2 + 1][k];
#pragma unroll
        for (int j = 0; j < 4; j++) {
            float xv = xs[rg * 4 + j][k];
            acc[j][0] += xv * w0;
            acc[j][1] += xv * w1;
        }
    }
#pragma unroll
    for (int j = 0; j < 4; j++) {
        int tb = tb0 + rg * 4 + j;
#pragma unroll
        for (int q = 0; q < 2; q++) {
            int h = h0 + hg * 2 + q;
            g_enc[(size_t)tb * NH + h] = acc[j][q] + enc_b[h];
        }
    }
}

// ---------------- persistent recurrent kernel ------------------------------------
// CTA: jt = bid>>4 (j-tile of 32 pairs), ks = bid&15 (k-slot of 64).
// Pair p = jt*32+jp: p<1024 -> (rec_w[p,:], fgt_w[p,:]); p>=1024 -> dec cols (2m,2m+1).
// Dataflow flags (no global barrier); hidden triple-buffered; partials parity-buffered.
__global__ void __launch_bounds__(NTHR, 4) persist_kernel(const float* __restrict__ rec_w,
                                                          const float* __restrict__ fgt_w,
                                                          const float* __restrict__ dec_w,
                                                          const float* __restrict__ dec_b,
                                                          float* __restrict__ out,
                                                          int writeHidden) {
    extern __shared__ __align__(16) char smem[];
    unsigned long long* ws = (unsigned long long*)smem;     // [64 k][32 jp] (wA,wB)
    float* hsf = (float*)(smem + KSL * JP_CTA * 8);         // [2][16 k][128 b]

    const int tid = threadIdx.x;
    const int bid = blockIdx.x;
    const int jt  = bid >> 4;        // 0..32
    const int ks  = bid & 15;        // 0..15
    const int j0  = jt * JP_CTA;
    const int kbase = ks * KSL;
    const bool isDec = (jt == 32);

    const int jg = tid & 7;          // 8 j-groups of 4 pairs
    const int bg = tid >> 3;         // 16 b-groups of 8 rows

    // ---- weights -> SMEM once ----
    for (int i = tid; i < KSL * JP_CTA; i += NTHR) {
        int k = i & (KSL - 1), jp = i >> 6;
        int p = j0 + jp;
        int gk = kbase + k;
        float a, b;
        if (p < 1024) { a = rec_w[p * NH + gk]; b = fgt_w[p * NH + gk]; }
        else { int m = p - 1024; a = dec_w[(2 * m) * NH + gk]; b = dec_w[(2 * m + 1) * NH + gk]; }
        ws[k * JP_CTA + jp] = ((unsigned long long)__float_as_uint(b) << 32) | __float_as_uint(a);
    }
    __syncthreads();

    // combine-phase identities: 16 CTAs of a jt cover 128 b; each thread: 1 b x 2 jp
    const int bloc = ks * 8 + (tid >> 4);    // b this thread combines
    const int jpb  = (tid & 15) * 2;         // 2 consecutive jp
    float2 db01 = make_float2(0, 0), db23 = db01;
    if (isDec) {
        db01 = *(const float2*)(dec_b + jpb * 2);
        db23 = *(const float2*)(dec_b + jpb * 2 + 2);
    }

    int cur = 0;
    for (int t = 0; t <= T_; t++) {
        const int nxt = (cur + 1 == 3) ? 0 : cur + 1;
        const bool work = (t < T_) || isDec;

        if (work) {
            // ---- wait: producer tiles of this k-slot reached level t ----
            if (tid == 0) {
                unsigned target = (unsigned)KSPLIT * (unsigned)t;
                while (((volatile unsigned*)g_done)[2 * ks]     < target) __nanosleep(20);
                while (((volatile unsigned*)g_done)[2 * ks + 1] < target) __nanosleep(20);
                __threadfence();
            }
            __syncthreads();

            // ================= GEMM over K-slice =================
            const float* __restrict__ hsrc = g_hidT[cur] + kbase * B_;
            float4 pf[4];
#pragma unroll
            for (int i = 0; i < 4; i++) {
                int slot = i * NTHR + tid;
                int row = slot >> 5, c4 = slot & 31;
                pf[i] = __ldcg((const float4*)(hsrc + row * B_ + c4 * 4));
            }
#pragma unroll
            for (int i = 0; i < 4; i++) {
                int slot = i * NTHR + tid;
                int row = slot >> 5, c4 = slot & 31;
                *(float4*)(hsf + row * B_ + c4 * 4) = pf[i];
            }

            ulonglong2 acc[8][2];
#pragma unroll
            for (int ib = 0; ib < 8; ib++)
#pragma unroll
                for (int jj = 0; jj < 2; jj++) { acc[ib][jj].x = 0ull; acc[ib][jj].y = 0ull; }

            for (int kc = 0; kc < NCHUNK; kc++) {
                if (kc + 1 < NCHUNK) {
#pragma unroll
                    for (int i = 0; i < 4; i++) {
                        int slot = i * NTHR + tid;
                        int row = slot >> 5, c4 = slot & 31;
                        pf[i] = __ldcg((const float4*)(hsrc + ((kc + 1) * BK + row) * B_ + c4 * 4));
                    }
                }
                __syncthreads();
                if (kc + 1 < NCHUNK) {
                    float* hb = hsf + ((kc + 1) & 1) * (BK * B_);
#pragma unroll
                    for (int i = 0; i < 4; i++) {
                        int slot = i * NTHR + tid;
                        int row = slot >> 5, c4 = slot & 31;
                        *(float4*)(hb + row * B_ + c4 * 4) = pf[i];
                    }
                }
                const float* hb = hsf + (kc & 1) * (BK * B_);
#pragma unroll
                for (int kk = 0; kk < BK; kk++) {
                    const float* hr = hb + kk * B_ + bg * 8;
                    float4 h0 = *(const float4*)hr;
                    float4 h1 = *(const float4*)(hr + 4);
                    const ulonglong2* wr = (const ulonglong2*)(ws + (kc * BK + kk) * JP_CTA + jg * 4);
                    ulonglong2 w0 = wr[0];
                    ulonglong2 w1 = wr[1];
                    unsigned long long d0 = dup2(h0.x), d1 = dup2(h0.y), d2 = dup2(h0.z), d3 = dup2(h0.w);
                    unsigned long long d4 = dup2(h1.x), d5 = dup2(h1.y), d6 = dup2(h1.z), d7 = dup2(h1.w);
                    FMA2(acc[0][0].x, d0, w0.x); FMA2(acc[0][0].y, d0, w0.y); FMA2(acc[0][1].x, d0, w1.x); FMA2(acc[0][1].y, d0, w1.y);
                    FMA2(acc[1][0].x, d1, w0.x); FMA2(acc[1][0].y, d1, w0.y); FMA2(acc[1][1].x, d1, w1.x); FMA2(acc[1][1].y, d1, w1.y);
                    FMA2(acc[2][0].x, d2, w0.x); FMA2(acc[2][0].y, d2, w0.y); FMA2(acc[2][1].x, d2, w1.x); FMA2(acc[2][1].y, d2, w1.y);
                    FMA2(acc[3][0].x, d3, w0.x); FMA2(acc[3][0].y, d3, w0.y); FMA2(acc[3][1].x, d3, w1.x); FMA2(acc[3][1].y, d3, w1.y);
                    FMA2(acc[4][0].x, d4, w0.x); FMA2(acc[4][0].y, d4, w0.y); FMA2(acc[4][1].x, d4, w1.x); FMA2(acc[4][1].y, d4, w1.y);
                    FMA2(acc[5][0].x, d5, w0.x); FMA2(acc[5][0].y, d5, w0.y); FMA2(acc[5][1].x, d5, w1.x); FMA2(acc[5][1].y, d5, w1.y);
                    FMA2(acc[6][0].x, d6, w0.x); FMA2(acc[6][0].y, d6, w0.y); FMA2(acc[6][1].x, d6, w1.x); FMA2(acc[6][1].y, d6, w1.y);
                    FMA2(acc[7][0].x, d7, w0.x); FMA2(acc[7][0].y, d7, w0.y); FMA2(acc[7][1].x, d7, w1.x); FMA2(acc[7][1].y, d7, w1.y);
                }
            }

            // ---- publish partials into step-parity slab ----
            unsigned long long* mypart = g_part + (size_t)(t & 1) * PARTBUF + (size_t)bid * OUTS_CTA;
#pragma unroll
            for (int ib = 0; ib < 8; ib++) {
                int b = bg * 8 + ib;
#pragma unroll
                for (int jj = 0; jj < 2; jj++)
                    *(ulonglong2*)(mypart + b * JP_CTA + jg * 4 + jj * 2) = acc[ib][jj];
            }
            __threadfence();
            __syncthreads();
            if (tid == 0) {
                if (isDec) atomicAdd(&g_decc[ks], 1u);   // hidden k-slice consumed
                atomicAdd(&g_flag[jt], 1u);
                unsigned target = (unsigned)KSPLIT * (unsigned)(t + 1);
                while (((volatile unsigned*)g_flag)[jt] < target) __nanosleep(20);
                if (!isDec && t >= 2) {                  // dec reader of buffer (t+1)%3 done?
                    unsigned dtarget = (unsigned)(t - 1);
                    while (((volatile unsigned*)g_decc)[jt >> 1] < dtarget) __nanosleep(20);
                }
                __threadfence();
            }
            __syncthreads();

            // ---- combine 16 k-slots + fused epilogue ----
            float R[2] = {0, 0}, F[2] = {0, 0};
            const unsigned long long* gp = g_part + (size_t)(t & 1) * PARTBUF +
                                           (size_t)(jt * KSPLIT) * OUTS_CTA + bloc * JP_CTA + jpb;
#pragma unroll
            for (int k2 = 0; k2 < KSPLIT; k2++) {
                uint4 q = __ldcg((const uint4*)(gp + (size_t)k2 * OUTS_CTA));
                R[0] += __uint_as_float(q.x); F[0] += __uint_as_float(q.y);
                R[1] += __uint_as_float(q.z); F[1] += __uint_as_float(q.w);
            }

            if (!isDec) {
                int hg0 = j0 + jpb;
                float2 e  = __ldcg((const float2*)(g_enc + (size_t)t * (B_ * NH) + bloc * NH + hg0));
                float2 ho = __ldcg((const float2*)(g_hidB[cur] + bloc * NH + hg0));
                const float ev[2]  = {e.x, e.y};
                const float hov[2] = {ho.x, ho.y};
                float hv[2];
#pragma unroll
                for (int i = 0; i < 2; i++) {
                    float f = 1.0f / (1.0f + __expf(-F[i]));
                    float s = ev[i] + R[i];
                    float hn = s / (1.0f + fabsf(s));
                    hv[i] = (1.0f - f) * hov[i] + f * hn;
                }
                *(float2*)(g_hidB[nxt] + bloc * NH + hg0) = make_float2(hv[0], hv[1]);
                g_hidT[nxt][(hg0 + 0) * B_ + bloc] = hv[0];
                g_hidT[nxt][(hg0 + 1) * B_ + bloc] = hv[1];

                // ---- signal: this tile's hidden share for step t+1 is ready ----
                __threadfence();
                __syncthreads();
                if (tid == 0) atomicAdd(&g_done[jt], 1u);
            } else if (t >= 1) {
                // pairs m=jpb, jpb+1 -> out cols 2*jpb .. 2*jpb+3
                float* op = out + (size_t)(t - 1) * (B_ * NO) + bloc * NO + jpb * 2;
                *(float2*)op       = make_float2(R[0] + db01.x, F[0] + db01.y);
                *(float2*)(op + 2) = make_float2(R[1] + db23.x, F[1] + db23.y);
            }
        }

        if (t == T_) break;
        cur = nxt;
    }

    // ---- final hidden copy: each rec CTA copies its tile's share ----
    if (writeHidden && !isDec) {
        if (tid == 0) {
            unsigned target = (unsigned)KSPLIT * (unsigned)T_;
            while (((volatile unsigned*)g_done)[jt] < target) __nanosleep(20);
            __threadfence();
        }
        __syncthreads();
        int b = ks * 8 + (tid >> 4);
        int h = jt * 32 + (tid & 15) * 2;
        float2 hv = *(const float2*)(g_hidB[cur] + b * NH + h);
        *(float2*)(out + (size_t)T_ * B_ * NO + (size_t)b * NH + h) = hv;
    }
}

// --------------------------------------------------------------------------------
extern "C" void kernel_launch(void* const* d_in, const int* in_sizes, int n_in,
                              void* d_out, int out_size) {
    const float* x       = (const float*)d_in[0];
    const float* enc_w   = (const float*)d_in[1];
    const float* enc_b   = (const float*)d_in[2];
    const float* rec_w   = (const float*)d_in[3];
    const float* fgt_w   = (const float*)d_in[4];
    const float* dec_w   = (const float*)d_in[5];
    const float* dec_b   = (const float*)d_in[6];
    const float* hinit_w = (const float*)d_in[7];
    const float* hinit_b = (const float*)d_in[8];
    float* out = (float*)d_out;

    reset_kernel<<<1, 64>>>();
    init_hidden_kernel<<<(B_ * NH + 255) / 256, 256>>>(hinit_w, hinit_b);

    dim3 eg(T_ * B_ / 32, NH / 64);
    enc_kernel<<<eg, 256>>>(x, enc_w, enc_b);

    cudaFuncSetAttribute(persist_kernel, cudaFuncAttributeMaxDynamicSharedMemorySize,
                         SMEM_BYTES);
    int writeHidden = (out_size >= T_ * B_ * NO + B_ * NH) ? 1 : 0;
    persist_kernel<<<NCTA, NTHR, SMEM_BYTES>>>(rec_w, fgt_w, dec_w, dec_b, out, writeHidden);
}